// round 17
// baseline (speedup 1.0000x reference)
#include <cuda_runtime.h>
#include <cuda_bf16.h>
#include <math.h>

// Problem constants
#define B_  8
#define L_  256
#define DM_ 1024
#define DI_ 2048
#define N_  16
#define K_  4
#define NL_ 4
#define DTR_ 128
#define P_  97
#define M_TOK (B_*L_)          // 2048 token rows
#define XPW_ (DTR_ + 2*N_)     // 160

// pair widths (k-pairs)
#define DMP (DM_/2)            // 512
#define DIP (DI_/2)            // 1024
#define DTRP (DTR_/2)          // 64
#define XPWP (XPW_/2)          // 80

// GEMM tiling
#define BM 128
#define BN 128
#define BKP 16                 // pairs per k-tile (= 32 k)
#define SST 132                // smem row stride in words ([kp][m] layout)
#define STGW (16*SST)          // words per stage per array
#define GEMM_DSM (8*STGW*4)    // 4 arrays x 2 stages = 67584 B

// ---------------- scratch (static device globals; no allocation) ----------------
__device__ __align__(16) float g_h [M_TOK*DM_];
__device__ __align__(16) float g_xz[M_TOK*2*DI_];
__device__ __align__(16) float g_xb[M_TOK*DI_];
__device__ __align__(16) float g_xp[M_TOK*XPW_];
__device__ __align__(16) float g_dl[M_TOK*DI_];
__device__ __align__(16) float g_fin[B_*DM_];
// packed activations: uint2 per k-pair = {hi bf16x2, lo bf16x2}
__device__ __align__(16) uint2 g_xP [M_TOK*DMP];
__device__ __align__(16) uint2 g_xbP[M_TOK*DIP];
__device__ __align__(16) uint2 g_xpP[M_TOK*XPWP];
__device__ __align__(16) uint2 g_yP [M_TOK*DIP];
// packed weights
__device__ __align__(16) uint2 g_ipwP[NL_*2*DI_*DMP];
__device__ __align__(16) uint2 g_xpwP[NL_*XPW_*DIP];
__device__ __align__(16) uint2 g_dtwP[NL_*DI_*DTRP];
__device__ __align__(16) uint2 g_opwP[NL_*DM_*DIP];

// ---------------- bf16 split (Dekker) ----------------
__device__ __forceinline__ uint2 split2_bf16(float x, float y) {
    __nv_bfloat16 hx = __float2bfloat16(x);
    __nv_bfloat16 hy = __float2bfloat16(y);
    float lx = x - __bfloat162float(hx);
    float ly = y - __bfloat162float(hy);
    __nv_bfloat162 hp = __halves2bfloat162(hx, hy);
    __nv_bfloat162 lp = __halves2bfloat162(__float2bfloat16(lx), __float2bfloat16(ly));
    unsigned hw = *reinterpret_cast<unsigned*>(&hp);
    unsigned lw = *reinterpret_cast<unsigned*>(&lp);
    return make_uint2(hw, lw);
}

__device__ __forceinline__ void mma_bf16(float* c, const unsigned* a, const unsigned* b) {
    asm volatile(
        "mma.sync.aligned.m16n8k16.row.col.f32.bf16.bf16.f32 "
        "{%0,%1,%2,%3}, {%4,%5,%6,%7}, {%8,%9}, {%0,%1,%2,%3};"
        : "+f"(c[0]), "+f"(c[1]), "+f"(c[2]), "+f"(c[3])
        : "r"(a[0]), "r"(a[1]), "r"(a[2]), "r"(a[3]), "r"(b[0]), "r"(b[1]));
}

__device__ __forceinline__ float softplus_f(float v) {
    return (v > 20.f) ? v : __logf(1.f + __expf(v));
}

// ---------------- generic fp32 -> packed split (grid-stride) ----------------
__global__ void pack_k(const float* __restrict__ src, uint2* __restrict__ dst, long npairs) {
    long i = (long)blockIdx.x * 256 + threadIdx.x;
    long stride = (long)gridDim.x * 256;
    for (; i < npairs; i += stride) {
        float2 v = reinterpret_cast<const float2*>(src)[i];
        dst[i] = split2_bf16(v.x, v.y);
    }
}

__global__ void zero_k(float* __restrict__ p, int n4) {
    int i = blockIdx.x * 256 + threadIdx.x;
    if (i < n4) reinterpret_cast<float4*>(p)[i] = make_float4(0,0,0,0);
}

// ---------------- embedding ----------------
__global__ void embed_k(const int* __restrict__ tok, const float* __restrict__ te,
                        const float* __restrict__ pe, float* __restrict__ h) {
    int row = blockIdx.x;
    int l = row & (L_ - 1);
    int t = tok[row];
    const float* tsrc = te + (long)t * DM_;
    const float* psrc = pe + (long)l * DM_;
    float* dst = h + (long)row * DM_;
    for (int d = threadIdx.x; d < DM_; d += 256)
        dst[d] = tsrc[d] + psrc[d];
}

// ---------------- layernorm -> packed (row of 1024, 256 thr, float4) ----------------
__global__ void ln_pack_k(const float* __restrict__ in,
                          const float* __restrict__ w, const float* __restrict__ bb,
                          uint2* __restrict__ outP) {
    __shared__ float red[8];
    __shared__ float s_mean, s_rstd;
    int t = threadIdx.x;
    int row = blockIdx.x;
    float4 v = reinterpret_cast<const float4*>(in + (long)row * DM_)[t];
    float s = v.x + v.y + v.z + v.w;
#pragma unroll
    for (int o = 16; o; o >>= 1) s += __shfl_xor_sync(~0u, s, o);
    if ((t & 31) == 0) red[t >> 5] = s;
    __syncthreads();
    if (t < 32) {
        float x = (t < 8) ? red[t] : 0.f;
#pragma unroll
        for (int o = 4; o; o >>= 1) x += __shfl_xor_sync(~0u, x, o);
        if (t == 0) s_mean = x * (1.f/DM_);
    }
    __syncthreads();
    float mean = s_mean;
    float dx = v.x-mean, dy = v.y-mean, dz = v.z-mean, dw = v.w-mean;
    float q = dx*dx + dy*dy + dz*dz + dw*dw;
#pragma unroll
    for (int o = 16; o; o >>= 1) q += __shfl_xor_sync(~0u, q, o);
    if ((t & 31) == 0) red[t >> 5] = q;
    __syncthreads();
    if (t < 32) {
        float x = (t < 8) ? red[t] : 0.f;
#pragma unroll
        for (int o = 4; o; o >>= 1) x += __shfl_xor_sync(~0u, x, o);
        if (t == 0) s_rstd = rsqrtf(x * (1.f/DM_) + 1e-5f);
    }
    __syncthreads();
    float r = s_rstd;
    float4 wv = reinterpret_cast<const float4*>(w)[t];
    float4 bv = reinterpret_cast<const float4*>(bb)[t];
    uint2 p0 = split2_bf16(dx * r * wv.x + bv.x, dy * r * wv.y + bv.y);
    uint2 p1 = split2_bf16(dz * r * wv.z + bv.z, dw * r * wv.w + bv.w);
    reinterpret_cast<uint4*>(outP)[(long)row * (DMP/2) + t] = make_uint4(p0.x, p0.y, p1.x, p1.y);
}

// ---------------- final layernorm (fp32 out) ----------------
__global__ void ln_k(const float* __restrict__ in, long istride,
                     float* __restrict__ out,
                     const float* __restrict__ w, const float* __restrict__ bb) {
    __shared__ float red[8];
    __shared__ float s_mean, s_rstd;
    int t = threadIdx.x;
    int row = blockIdx.x;
    const float* src = in + (long)row * istride;
    float v[4];
    float s = 0.f;
#pragma unroll
    for (int i = 0; i < 4; i++) { v[i] = src[t + i*256]; s += v[i]; }
#pragma unroll
    for (int o = 16; o; o >>= 1) s += __shfl_xor_sync(~0u, s, o);
    if ((t & 31) == 0) red[t >> 5] = s;
    __syncthreads();
    if (t < 32) {
        float x = (t < 8) ? red[t] : 0.f;
#pragma unroll
        for (int o = 4; o; o >>= 1) x += __shfl_xor_sync(~0u, x, o);
        if (t == 0) s_mean = x * (1.f/DM_);
    }
    __syncthreads();
    float mean = s_mean;
    float q = 0.f;
#pragma unroll
    for (int i = 0; i < 4; i++) { float d = v[i] - mean; q += d * d; }
#pragma unroll
    for (int o = 16; o; o >>= 1) q += __shfl_xor_sync(~0u, q, o);
    if ((t & 31) == 0) red[t >> 5] = q;
    __syncthreads();
    if (t < 32) {
        float x = (t < 8) ? red[t] : 0.f;
#pragma unroll
        for (int o = 4; o; o >>= 1) x += __shfl_xor_sync(~0u, x, o);
        if (t == 0) s_rstd = rsqrtf(x * (1.f/DM_) + 1e-5f);
    }
    __syncthreads();
    float r = s_rstd;
#pragma unroll
    for (int i = 0; i < 4; i++) {
        int idx = t + i*256;
        out[(long)row * DM_ + idx] = (v[i] - mean) * r * w[idx] + bb[idx];
    }
}

// ---------------- GEMM macros (packed operands) ----------------
// load one 16-k chunk (8 pairs): each thread 1 uint4 per row = 2 pairs at kp0
#define GEMM_LOAD_DEPOSIT(AH, AL, BH, BL, KOFFP, ROWB)                                 \
    {                                                                                  \
        uint4 a0 = aOK0 ? *(const uint4*)(Ap0 + (KOFFP)) : z4u;                        \
        uint4 a1 = aOK1 ? *(const uint4*)(Ap1 + (KOFFP)) : z4u;                        \
        uint4 b0 = bOK0 ? *(const uint4*)(Wp0 + (KOFFP)) : z4u;                        \
        uint4 b1 = bOK1 ? *(const uint4*)(Wp1 + (KOFFP)) : z4u;                        \
        AH[((ROWB)+kp0)*SST + r0]      = a0.x; AL[((ROWB)+kp0)*SST + r0]      = a0.y;  \
        AH[((ROWB)+kp0+1)*SST + r0]    = a0.z; AL[((ROWB)+kp0+1)*SST + r0]    = a0.w;  \
        AH[((ROWB)+kp0)*SST + r0+64]   = a1.x; AL[((ROWB)+kp0)*SST + r0+64]   = a1.y;  \
        AH[((ROWB)+kp0+1)*SST + r0+64] = a1.z; AL[((ROWB)+kp0+1)*SST + r0+64] = a1.w;  \
        BH[((ROWB)+kp0)*SST + r0]      = b0.x; BL[((ROWB)+kp0)*SST + r0]      = b0.y;  \
        BH[((ROWB)+kp0+1)*SST + r0]    = b0.z; BL[((ROWB)+kp0+1)*SST + r0]    = b0.w;  \
        BH[((ROWB)+kp0)*SST + r0+64]   = b1.x; BL[((ROWB)+kp0)*SST + r0+64]   = b1.y;  \
        BH[((ROWB)+kp0+1)*SST + r0+64] = b1.z; BL[((ROWB)+kp0+1)*SST + r0+64] = b1.w;  \
    }

#define GEMM_COMPUTE(AH, AL, BH, BL, KPOFF)                                            \
    {                                                                                  \
        int krow = (KPOFF) + tig;                                                      \
        unsigned bh[4][2], bl[4][2];                                                   \
        _Pragma("unroll")                                                              \
        for (int j = 0; j < 4; j++) {                                                  \
            int n = warpN + j*8 + grp;                                                 \
            bh[j][0] = BH[krow*SST + n];                                               \
            bh[j][1] = BH[(krow+4)*SST + n];                                           \
            bl[j][0] = BL[krow*SST + n];                                               \
            bl[j][1] = BL[(krow+4)*SST + n];                                           \
        }                                                                              \
        _Pragma("unroll")                                                              \
        for (int i = 0; i < 4; i++) {                                                  \
            int m = warpM + i*16 + grp;                                                \
            unsigned ah[4], al[4];                                                     \
            ah[0] = AH[krow*SST + m];     ah[1] = AH[krow*SST + m + 8];                \
            ah[2] = AH[(krow+4)*SST + m]; ah[3] = AH[(krow+4)*SST + m + 8];            \
            al[0] = AL[krow*SST + m];     al[1] = AL[krow*SST + m + 8];                \
            al[2] = AL[(krow+4)*SST + m]; al[3] = AL[(krow+4)*SST + m + 8];            \
            _Pragma("unroll")                                                          \
            for (int j = 0; j < 4; j++) mma_bf16(acc[i][j], ah, bh[j]);                \
            _Pragma("unroll")                                                          \
            for (int j = 0; j < 4; j++) mma_bf16(acc[i][j], ah, bl[j]);                \
            _Pragma("unroll")                                                          \
            for (int j = 0; j < 4; j++) mma_bf16(acc[i][j], al, bh[j]);                \
        }                                                                              \
    }

#define GEMM_PREAMBLE(ABASE, WBASE, LDAP, LDBP, MM, NN)                                \
    extern __shared__ unsigned dynsm[];                                                \
    unsigned* AHb = dynsm;                                                             \
    unsigned* ALb = dynsm + 2*STGW;                                                    \
    unsigned* BHb = dynsm + 4*STGW;                                                    \
    unsigned* BLb = dynsm + 6*STGW;                                                    \
    int tid = threadIdx.x;                                                             \
    int lane = tid & 31, wid = tid >> 5;                                               \
    int warpM = (wid >> 2) * 64;                                                       \
    int warpN = (wid & 3) * 32;                                                        \
    int grp = lane >> 2, tig = lane & 3;                                               \
    int r0 = tid >> 2;                                                                 \
    int kp0 = (tid & 3) * 2;                                                           \
    int gAr0 = blockIdx.y * BM + r0, gAr1 = gAr0 + 64;                                 \
    int gBr0 = blockIdx.x * BN + r0, gBr1 = gBr0 + 64;                                 \
    bool aOK0 = gAr0 < (MM), aOK1 = gAr1 < (MM);                                       \
    bool bOK0 = gBr0 < (NN), bOK1 = gBr1 < (NN);                                       \
    const uint2* Ap0 = (ABASE) + (long)gAr0 * (LDAP) + kp0;                            \
    const uint2* Ap1 = (ABASE) + (long)gAr1 * (LDAP) + kp0;                            \
    const uint2* Wp0 = (WBASE) + (long)gBr0 * (LDBP) + kp0;                            \
    const uint2* Wp1 = (WBASE) + (long)gBr1 * (LDBP) + kp0;                            \
    float acc[4][4][4];                                                                \
    _Pragma("unroll")                                                                  \
    for (int i = 0; i < 4; i++)                                                        \
        _Pragma("unroll")                                                              \
        for (int j = 0; j < 4; j++)                                                    \
            _Pragma("unroll")                                                          \
            for (int q = 0; q < 4; q++) acc[i][j][q] = 0.f;                            \
    const uint4 z4u = make_uint4(0,0,0,0);                                             \
    GEMM_LOAD_DEPOSIT(AHb, ALb, BHb, BLb, 0, 0);                                       \
    GEMM_LOAD_DEPOSIT(AHb, ALb, BHb, BLb, 8, 8);                                       \
    __syncthreads();

#define GEMM_MAINLOOP(NST)                                                             \
    for (int kt = 0; kt < (NST); kt++) {                                               \
        int cur = kt & 1, nxt = cur ^ 1;                                               \
        bool pf = (kt + 1) < (NST);                                                    \
        unsigned* cAH = AHb + cur*STGW; unsigned* cAL = ALb + cur*STGW;                \
        unsigned* cBH = BHb + cur*STGW; unsigned* cBL = BLb + cur*STGW;                \
        if (pf) {                                                                      \
            int k0 = (kt + 1) * BKP;                                                   \
            unsigned* nAH = AHb + nxt*STGW; unsigned* nAL = ALb + nxt*STGW;            \
            unsigned* nBH = BHb + nxt*STGW; unsigned* nBL = BLb + nxt*STGW;            \
            GEMM_LOAD_DEPOSIT(nAH, nAL, nBH, nBL, k0, 0);                              \
            GEMM_LOAD_DEPOSIT(nAH, nAL, nBH, nBL, k0 + 8, 8);                          \
        }                                                                              \
        GEMM_COMPUTE(cAH, cAL, cBH, cBL, 0);                                           \
        GEMM_COMPUTE(cAH, cAL, cBH, cBL, 8);                                           \
        if (pf) __syncthreads();                                                       \
    }

// ---------------- packed compensated GEMM (BKP=16 pairs/tile) ----------------
__global__ __launch_bounds__(256, 2)
void gemm_p(int M, int N, int KdP,
            const uint2* __restrict__ A, int ldaP,
            const uint2* __restrict__ W, int ldbP,
            float* __restrict__ C, int ldc,
            const float* __restrict__ bias,
            const float* __restrict__ add, int ldadd,
            int act) {
    GEMM_PREAMBLE(A, W, ldaP, ldbP, M, N);
    GEMM_MAINLOOP(KdP / BKP);

#pragma unroll
    for (int i = 0; i < 4; i++) {
        int gm0 = blockIdx.y * BM + warpM + i*16 + grp;
#pragma unroll
        for (int j = 0; j < 4; j++) {
            int gn = blockIdx.x * BN + warpN + j*8 + 2*tig;
#pragma unroll
            for (int half = 0; half < 2; half++) {
                int gm = gm0 + half*8;
                if (gm >= M) continue;
#pragma unroll
                for (int q = 0; q < 2; q++) {
                    int n = gn + q;
                    if (n >= N) continue;
                    float v = acc[i][j][half*2 + q];
                    if (bias) v += bias[n];
                    if (act == 1) v = softplus_f(v);
                    if (add) v += add[(long)gm * ldadd + n];
                    C[(long)gm * ldc + n] = v;
                }
            }
        }
    }
}

// ---------------- packed split-K GEMM: C += partial (atomicAdd) ----------------
__global__ __launch_bounds__(256, 2)
void gemm_p_sk(int M, int N, int kcntP,
               const uint2* __restrict__ A, int ldaP,
               const uint2* __restrict__ W, int ldbP,
               float* __restrict__ C, int ldc) {
    long kbeg = (long)blockIdx.z * kcntP;
    const uint2* Ab = A + kbeg;
    const uint2* Wb = W + kbeg;
    GEMM_PREAMBLE(Ab, Wb, ldaP, ldbP, M, N);
    GEMM_MAINLOOP(kcntP / BKP);

#pragma unroll
    for (int i = 0; i < 4; i++) {
        int gm0 = blockIdx.y * BM + warpM + i*16 + grp;
#pragma unroll
        for (int j = 0; j < 4; j++) {
            int gn = blockIdx.x * BN + warpN + j*8 + 2*tig;
#pragma unroll
            for (int half = 0; half < 2; half++) {
                int gm = gm0 + half*8;
                if (gm >= M) continue;
#pragma unroll
                for (int q = 0; q < 2; q++) {
                    int n = gn + q;
                    if (n >= N) continue;
                    atomicAdd(&C[(long)gm * ldc + n], acc[i][j][half*2 + q]);
                }
            }
        }
    }
}

// ---------------- causal depthwise conv (K=4) + SiLU -> fp32 + packed ----------------
// one thread per d-pair
__global__ void conv_silu_k(const float* __restrict__ xz, const float* __restrict__ cw,
                            const float* __restrict__ cb, float* __restrict__ xb,
                            uint2* __restrict__ xbP) {
    long pidx = (long)blockIdx.x * 256 + threadIdx.x;   // < M_TOK*DIP
    int ep = (int)(pidx & (DIP - 1));
    long bl = pidx >> 10;                // / DIP
    int l = (int)(bl & (L_ - 1));
    int d0 = ep * 2, d1 = d0 + 1;
    float a0 = cb[d0], a1 = cb[d1];
#pragma unroll
    for (int k = 0; k < K_; k++) {
        int lp = l + k - (K_ - 1);
        if (lp >= 0) {
            const float* src = xz + (bl + (k - (K_-1))) * (2*DI_);
            a0 = fmaf(cw[d0*K_ + k], src[d0], a0);
            a1 = fmaf(cw[d1*K_ + k], src[d1], a1);
        }
    }
    a0 = __fdividef(a0, 1.f + __expf(-a0));
    a1 = __fdividef(a1, 1.f + __expf(-a1));
    reinterpret_cast<float2*>(xb)[pidx] = make_float2(a0, a1);
    xbP[pidx] = split2_bf16(a0, a1);
}

// ---------------- selective SSM scan + D skip + z-gating -> packed y ----------------
// 16 lanes per channel; warp covers channels d (even) and d+1; lane0 writes the pair.
__global__ void ssm_scan_k(const float* __restrict__ xb, const float* __restrict__ xp,
                           const float* __restrict__ dl, const float* __restrict__ xz,
                           const float* __restrict__ Alog, const float* __restrict__ Dp,
                           uint2* __restrict__ yP) {
    int t = threadIdx.x;
    int g = t >> 4, lane = t & 15;
    int ch = blockIdx.x * 16 + g;
    int b = ch >> 11;
    int d = ch & (DI_ - 1);
    float A = -__expf(Alog[d*N_ + lane]);
    float Dv = Dp[d];
    float h = 0.f;
    long rowbase = (long)b * L_;
    const float* dlp = dl + rowbase*DI_ + d;
    const float* xbp = xb + rowbase*DI_ + d;
    const float* Bp  = xp + rowbase*XPW_ + DTR_ + lane;
    const float* zp  = xz + rowbase*(2*DI_) + DI_ + d;
    uint2* ypP = yP + rowbase*DIP + (d >> 1);
    for (int l = 0; l < L_; l++) {
        float dv = dlp[(long)l*DI_];
        float xv = xbp[(long)l*DI_];
        float Bv = Bp[(long)l*XPW_];
        float Cv = Bp[(long)l*XPW_ + N_];
        h = fmaf(__expf(dv * A), h, dv * Bv * xv);
        float c = h * Cv;
        c += __shfl_xor_sync(~0u, c, 8);
        c += __shfl_xor_sync(~0u, c, 4);
        c += __shfl_xor_sync(~0u, c, 2);
        c += __shfl_xor_sync(~0u, c, 1);
        float v = 0.f;
        if (lane == 0) {
            float z = zp[(long)l*(2*DI_)];
            float yv = c + xv * Dv;
            v = yv * __fdividef(z, 1.f + __expf(-z));
        }
        float pv = __shfl_xor_sync(~0u, v, 16);   // lane0 of even group gets odd group's v
        if ((t & 31) == 0)
            ypP[(long)l*DIP] = split2_bf16(v, pv);
    }
}

// ---------------- head ----------------
__global__ void head_k(const float* __restrict__ fin, const float* __restrict__ hw,
                       float* __restrict__ out) {
    int wid = blockIdx.x * 8 + (threadIdx.x >> 5);
    int lane = threadIdx.x & 31;
    if (wid >= B_ * P_) return;
    int b = wid / P_, p = wid % P_;
    const float* a = fin + (long)b * DM_;
    const float* w = hw + (long)p * DM_;
    float s = 0.f;
    for (int k = lane; k < DM_; k += 32) s = fmaf(a[k], w[k], s);
#pragma unroll
    for (int o = 16; o; o >>= 1) s += __shfl_xor_sync(~0u, s, o);
    if (lane == 0) out[wid] = s;
}

// ---------------- launch ----------------
extern "C" void kernel_launch(void* const* d_in, const int* in_sizes, int n_in,
                              void* d_out, int out_size) {
    const int*   tokens    = (const int*)  d_in[0];
    const float* tok_emb   = (const float*)d_in[1];
    const float* pos_emb   = (const float*)d_in[2];
    const float* ln_w      = (const float*)d_in[3];
    const float* ln_b      = (const float*)d_in[4];
    const float* in_proj_w = (const float*)d_in[5];
    const float* conv_w    = (const float*)d_in[6];
    const float* conv_b    = (const float*)d_in[7];
    const float* xproj_w   = (const float*)d_in[8];
    const float* dt_w      = (const float*)d_in[9];
    const float* dt_b      = (const float*)d_in[10];
    const float* A_log     = (const float*)d_in[11];
    const float* D_param   = (const float*)d_in[12];
    const float* out_proj_w= (const float*)d_in[13];
    const float* fnorm_w   = (const float*)d_in[14];
    const float* fnorm_b   = (const float*)d_in[15];
    const float* head_w    = (const float*)d_in[16];
    float* out = (float*)d_out;

    cudaFuncSetAttribute(gemm_p,    cudaFuncAttributeMaxDynamicSharedMemorySize, GEMM_DSM);
    cudaFuncSetAttribute(gemm_p_sk, cudaFuncAttributeMaxDynamicSharedMemorySize, GEMM_DSM);

    void *ph, *pxz, *pxb, *pxp, *pdl, *pfin;
    void *pxP, *pxbP, *pxpP, *pyP, *pipw, *pxpw, *pdtw, *popw;
    cudaGetSymbolAddress(&ph,  g_h);
    cudaGetSymbolAddress(&pxz, g_xz);
    cudaGetSymbolAddress(&pxb, g_xb);
    cudaGetSymbolAddress(&pxp, g_xp);
    cudaGetSymbolAddress(&pdl, g_dl);
    cudaGetSymbolAddress(&pfin,g_fin);
    cudaGetSymbolAddress(&pxP, g_xP);
    cudaGetSymbolAddress(&pxbP,g_xbP);
    cudaGetSymbolAddress(&pxpP,g_xpP);
    cudaGetSymbolAddress(&pyP, g_yP);
    cudaGetSymbolAddress(&pipw,g_ipwP);
    cudaGetSymbolAddress(&pxpw,g_xpwP);
    cudaGetSymbolAddress(&pdtw,g_dtwP);
    cudaGetSymbolAddress(&popw,g_opwP);
    float* h  = (float*)ph;   float* xz = (float*)pxz;
    float* xb = (float*)pxb;  float* xp = (float*)pxp;
    float* dl = (float*)pdl;  float* fin= (float*)pfin;
    uint2* xP  = (uint2*)pxP;   uint2* xbP = (uint2*)pxbP;
    uint2* xpP = (uint2*)pxpP;  uint2* yP  = (uint2*)pyP;
    uint2* ipwP= (uint2*)pipw;  uint2* xpwP= (uint2*)pxpw;
    uint2* dtwP= (uint2*)pdtw;  uint2* opwP= (uint2*)popw;

    // pack weights (once per launch — required each call; ~40us total)
    pack_k<<<4096, 256>>>(in_proj_w, ipwP, (long)NL_*2*DI_*DMP);
    pack_k<<<2048, 256>>>(xproj_w,   xpwP, (long)NL_*XPW_*DIP);
    pack_k<<<2048, 256>>>(dt_w,      dtwP, (long)NL_*DI_*DTRP);
    pack_k<<<4096, 256>>>(out_proj_w,opwP, (long)NL_*DM_*DIP);

    embed_k<<<M_TOK, 256>>>(tokens, tok_emb, pos_emb, h);

    for (int i = 0; i < NL_; i++) {
        // 1. layernorm -> packed x
        ln_pack_k<<<M_TOK, 256>>>(h, ln_w + i*DM_, ln_b + i*DM_, xP);
        // 2. in_proj: 2048 x 4096 x (512 pairs)
        gemm_p<<<dim3(32, 16), 256, GEMM_DSM>>>(M_TOK, 2*DI_, DMP,
            xP, DMP, ipwP + (long)i*2*DI_*DMP, DMP,
            xz, 2*DI_, nullptr, nullptr, 0, 0);
        // 3. conv + silu -> xb fp32 + packed
        conv_silu_k<<<(M_TOK*DIP)/256, 256>>>(xz, conv_w + (long)i*DI_*K_,
            conv_b + (long)i*DI_, xb, xbP);
        // 4. xproj: split-K 8 (128 pairs each), atomic into zeroed xp
        zero_k<<<(M_TOK*XPW_/4 + 255)/256, 256>>>(xp, M_TOK*XPW_/4);
        gemm_p_sk<<<dim3(2, 16, 8), 256, GEMM_DSM>>>(M_TOK, XPW_, DIP/8,
            xbP, DIP, xpwP + (long)i*XPW_*DIP, DIP,
            xp, XPW_);
        // 5. pack xp -> xpP (dt_r lives in pairs 0..63 of each row)
        pack_k<<<640, 256>>>(xp, xpP, (long)M_TOK*XPWP);
        // 6. delta = softplus(dt_r @ dtw.T + dtb): Kd = 64 pairs
        gemm_p<<<dim3(16, 16), 256, GEMM_DSM>>>(M_TOK, DI_, DTRP,
            xpP, XPWP, dtwP + (long)i*DI_*DTRP, DTRP,
            dl, DI_, dt_b + (long)i*DI_, nullptr, 0, 1);
        // 7. SSM scan -> packed y
        ssm_scan_k<<<(B_*DI_)/16, 256>>>(xb, xp, dl, xz,
            A_log + (long)i*DI_*N_, D_param + (long)i*DI_, yP);
        // 8. out_proj + residual: split-K 2 (512 pairs each), atomic into h
        gemm_p_sk<<<dim3(8, 16, 2), 256, GEMM_DSM>>>(M_TOK, DM_, DIP/2,
            yP, DIP, opwP + (long)i*DM_*DIP, DIP,
            h, DM_);
    }

    ln_k<<<B_, 256>>>(h + (long)(L_-1)*DM_, (long)L_*DM_, fin, fnorm_w, fnorm_b);
    head_k<<<P_, 256>>>(fin, head_w, out);
}